// round 9
// baseline (speedup 1.0000x reference)
#include <cuda_runtime.h>

typedef unsigned long long u64;
static const unsigned FULL = 0xFFFFFFFFu;

// ---- packed f32x2 helpers ----
__device__ __forceinline__ u64 pk2(float lo, float hi) {
    u64 r;
    asm("mov.b64 %0, {%1, %2};" : "=l"(r) : "f"(lo), "f"(hi));
    return r;
}
__device__ __forceinline__ void upk2(u64 a, float& lo, float& hi) {
    asm("mov.b64 {%0, %1}, %2;" : "=f"(lo), "=f"(hi) : "l"(a));
}
__device__ __forceinline__ u64 fma2(u64 a, u64 b, u64 c) {
    u64 d;
    asm("fma.rn.f32x2 %0, %1, %2, %3;" : "=l"(d) : "l"(a), "l"(b), "l"(c));
    return d;
}
__device__ __forceinline__ u64 mul2(u64 a, u64 b) {
    u64 d;
    asm("mul.rn.f32x2 %0, %1, %2;" : "=l"(d) : "l"(a), "l"(b));
    return d;
}

__host__ __device__ constexpr int PC4(int t) {
    return (t & 1) + ((t >> 1) & 1) + ((t >> 2) & 1) + ((t >> 3) & 1);
}
__host__ __device__ constexpr int PC3(int a) {
    return (a & 1) + ((a >> 1) & 1) + ((a >> 2) & 1);
}

// group index helpers (must match main loop enumeration order: a asc, b asc)
__device__ int e_index(int a, int b) {
    int k = 0;
    for (int aa = 0; aa < 8; aa++)
        for (int bb = aa + 1; bb < 8; bb++)
            if (((PC3(aa) ^ PC3(bb)) & 1) == 0) {
                if (aa == a && bb == b) return k;
                k++;
            }
    return 0;
}
__device__ int o_index(int a, int b) {
    int k = 0;
    for (int aa = 0; aa < 8; aa++)
        for (int bb = aa + 1; bb < 8; bb++)
            if (((PC3(aa) ^ PC3(bb)) & 1) == 1) {
                if (aa == a && bb == b) return k;
                k++;
            }
    return 0;
}

// ---------------------------------------------------------------------------
// Fused kernel, 512 threads/block, one sample per thread.
// Phase 0 (hoisted): per-sample sincos(x) + packed T-vector build — independent
//   of the coefficient table, so it executes in the shuffle-stall shadow of
//   phase 1.
// Phase 1 (prep, 16 warps): warp t propagates real basis column t through the
//   fixed circuit via warp shuffles (2 amps/lane: b = (lane<<1)|r).
// Phase 2 (256 threads): bake quadratic-form coefficients, LDS.128-vectorized
//   (b-groups of 4 share all four output signs).
// Phase 3: 36 packed group FMAs against the shared coefficient table.
// ---------------------------------------------------------------------------
__global__ void __launch_bounds__(512) qfused_kernel(
    const float* __restrict__ x,
    const float* __restrict__ W,
    const float* __restrict__ ab,
    float* __restrict__ out,
    int nlayers, int B)
{
    __shared__ __align__(16) float sM[16][68];   // 68: rows stay 16B-aligned
    __shared__ __align__(16) float sC[36 * 8];

    const int tid = threadIdx.x;
    const int lane = tid & 31;
    const int wp = tid >> 5;  // warp id = basis column index t (bit3 = qubit0)
    const int gid = blockIdx.x * 512 + tid;

    // ---------------- Phase 0: sample load + T-vector build (hoisted) -------
    float4 xv = make_float4(0.f, 0.f, 0.f, 0.f);
    if (gid < B) xv = reinterpret_cast<const float4*>(x)[gid];

    float c0, s0, c1, s1, c2, s2, c3, s3;
    __sincosf(0.5f * xv.x, &s0, &c0);
    __sincosf(0.5f * xv.y, &s1, &c1);
    __sincosf(0.5f * xv.z, &s2, &c2);
    __sincosf(0.5f * xv.w, &s3, &c3);

    float f0[2] = {c0, s0}, f1[2] = {c1, s1}, f2[2] = {c2, s2};
    float t2a[4], t3a[8];
#pragma unroll
    for (int a = 0; a < 2; a++)
#pragma unroll
        for (int b = 0; b < 2; b++) t2a[a * 2 + b] = f0[a] * f1[b];
#pragma unroll
    for (int a = 0; a < 4; a++)
#pragma unroll
        for (int b = 0; b < 2; b++) t3a[a * 2 + b] = t2a[a] * f2[b];

    const u64 cs3 = pk2(c3, s3);
    const u64 sc3 = pk2(s3, c3);
    u64 Tp[8], Ts[8];  // Tp[a] = (T[2a], T[2a+1]),  Ts[a] = swapped
#pragma unroll
    for (int a = 0; a < 8; a++) {
        u64 dd = pk2(t3a[a], t3a[a]);
        Tp[a] = mul2(dd, cs3);
        Ts[a] = mul2(dd, sc3);
    }

    // ---------------- Phase 1: shuffle-based column propagation ----------------
    {
        float ca0, sa0, ca1, sa1;
        __sincosf(0.5f * __ldg(&ab[0]), &sa0, &ca0);
        __sincosf(0.5f * __ldg(&ab[1]), &sa1, &ca1);
        // ancilla amp A[(q4<<1)|q5]
        float Ae0 = ca0 * ca1, Ae1 = ca0 * sa1;  // q4=0
        float Ao0 = sa0 * ca1, Ao1 = sa0 * sa1;  // q4=1
        const bool hit = ((lane >> 1) == wp);    // lane bits 4..1 = qubits 0..3
        float r0, r1;
        if (lane & 1) { r0 = hit ? Ao0 : 0.f; r1 = hit ? Ao1 : 0.f; }
        else          { r0 = hit ? Ae0 : 0.f; r1 = hit ? Ae1 : 0.f; }

        for (int l = 0; l < nlayers; l++) {
            // hoisted per-layer weight sincos (independent MUFUs)
            float ws[6], wc[6];
#pragma unroll
            for (int w = 0; w < 6; w++)
                __sincosf(0.5f * __ldg(&W[l * 6 + w]), &ws[w], &wc[w]);

            // CNOT ring: (0,1)(1,2)(2,3)(3,4) in lane bits
#pragma unroll
            for (int w = 0; w < 4; w++) {
                const int cm = 16 >> w, tm = 8 >> w;
                float t0 = __shfl_xor_sync(FULL, r0, tm);
                float t1 = __shfl_xor_sync(FULL, r1, tm);
                if (lane & cm) { r0 = t0; r1 = t1; }
            }
            // (4,5): control lane bit0, target in-register
            if (lane & 1) { float t = r0; r0 = r1; r1 = t; }
            // (5,0): control r-index, target lane bit4
            r1 = __shfl_xor_sync(FULL, r1, 16);
            // RY on qubits 0..4 (lane bits), then qubit 5 (in-register)
#pragma unroll
            for (int w = 0; w < 5; w++) {
                const int m = 16 >> w;
                float o0 = __shfl_xor_sync(FULL, r0, m);
                float o1 = __shfl_xor_sync(FULL, r1, m);
                float sg = (lane & m) ? ws[w] : -ws[w];
                r0 = fmaf(sg, o0, wc[w] * r0);
                r1 = fmaf(sg, o1, wc[w] * r1);
            }
            {
                float n0 = fmaf(-ws[5], r1, wc[5] * r0);
                float n1 = fmaf(ws[5], r0, wc[5] * r1);
                r0 = n0; r1 = n1;
            }
        }
        sM[wp][2 * lane]     = r0;  // b bit0 = qubit5
        sM[wp][2 * lane + 1] = r1;
    }
    __syncthreads();

    // ---------------- Phase 2: coefficient table (LDS.128-vectorized) --------
    if (tid < 256) {
        const int t = tid >> 4, tb = tid & 15;
        if (t <= tb && (((PC4(t) ^ PC4(tb)) & 1) == 0)) {
            float a0 = 0.f, a1 = 0.f, a2 = 0.f, a3 = 0.f;
#pragma unroll
            for (int i = 0; i < 16; i++) {
                // b-group of 4 (b = 4i..4i+3) shares all four output signs
                float4 u = *reinterpret_cast<const float4*>(&sM[t][4 * i]);
                float4 v = *reinterpret_cast<const float4*>(&sM[tb][4 * i]);
                float pr = u.x * v.x + u.y * v.y + u.z * v.z + u.w * v.w;
                const int b = 4 * i;
                a0 += (b & 32) ? -pr : pr;  // qubit 0
                a1 += (b & 16) ? -pr : pr;  // qubit 1
                a2 += (b & 8)  ? -pr : pr;  // qubit 2
                a3 += (b & 4)  ? -pr : pr;  // qubit 3
            }
            const int d = (PC4(t) - PC4(tb)) & 3;  // chi = +1 (d==0) / -1 (d==2)
            const float f = (d == 0 ? 1.f : -1.f) * (t == tb ? 1.f : 2.f);
            const int a = t >> 1, i2 = t & 1, b2 = tb >> 1, jj = tb & 1;
            int j, slot;
            if (a == b2)       { j = a;                   slot = i2; }  // diag group
            else if (i2 == jj) { j = 8 + e_index(a, b2);  slot = i2; }  // E group
            else               { j = 20 + o_index(a, b2); slot = i2; }  // O group
            sC[j * 8 + 0 + slot] = f * a0;
            sC[j * 8 + 2 + slot] = f * a1;
            sC[j * 8 + 4 + slot] = f * a2;
            sC[j * 8 + 6 + slot] = f * a3;
        }
    }
    __syncthreads();

    // ---------------- Phase 3: per-sample quadratic form ----------------
    if (gid >= B) return;

    u64 acc0 = 0ULL, acc1 = 0ULL, acc2 = 0ULL, acc3 = 0ULL;

#define ACCUM(J, PP) do {                                                     \
        u64 pp_ = (PP);                                                       \
        const ulonglong2* q_ = reinterpret_cast<const ulonglong2*>(&sC[(J) * 8]); \
        ulonglong2 qa_ = q_[0], qb_ = q_[1];                                  \
        acc0 = fma2(qa_.x, pp_, acc0);                                        \
        acc1 = fma2(qa_.y, pp_, acc1);                                        \
        acc2 = fma2(qb_.x, pp_, acc2);                                        \
        acc3 = fma2(qb_.y, pp_, acc3);                                        \
    } while (0)

    // diag groups j = 0..7:  (T2a^2, T2a+1^2)
#pragma unroll
    for (int a = 0; a < 8; a++) ACCUM(a, mul2(Tp[a], Tp[a]));
    // E groups j = 8..19: (T2a*T2b, T2a+1*T2b+1), same pc3 parity
    {
        int j = 8;
#pragma unroll
        for (int a = 0; a < 8; a++)
#pragma unroll
            for (int b = a + 1; b < 8; b++)
                if (((PC3(a) ^ PC3(b)) & 1) == 0) { ACCUM(j, mul2(Tp[a], Tp[b])); j++; }
    }
    // O groups j = 20..35: (T2a*T2b+1, T2a+1*T2b), different pc3 parity
    {
        int j = 20;
#pragma unroll
        for (int a = 0; a < 8; a++)
#pragma unroll
            for (int b = a + 1; b < 8; b++)
                if (((PC3(a) ^ PC3(b)) & 1) == 1) { ACCUM(j, mul2(Tp[a], Ts[b])); j++; }
    }
#undef ACCUM

    float lo, hi;
    float4 o;
    upk2(acc0, lo, hi); o.x = lo + hi;
    upk2(acc1, lo, hi); o.y = lo + hi;
    upk2(acc2, lo, hi); o.z = lo + hi;
    upk2(acc3, lo, hi); o.w = lo + hi;
    reinterpret_cast<float4*>(out)[gid] = o;
}

extern "C" void kernel_launch(void* const* d_in, const int* in_sizes, int n_in,
                              void* d_out, int out_size) {
    const float* x  = (const float*)d_in[0];   // (B, 4)
    const float* W  = (const float*)d_in[1];   // (NL, 6)
    const float* ab = (const float*)d_in[2];   // (2,)
    float* out = (float*)d_out;                // (B, 4)
    const int B = in_sizes[0] / 4;
    const int nlayers = in_sizes[1] / 6;
    const int threads = 512;
    const int blocks = (B + threads - 1) / threads;
    qfused_kernel<<<blocks, threads>>>(x, W, ab, out, nlayers, B);
}

// round 10
// speedup vs baseline: 1.0332x; 1.0332x over previous
#include <cuda_runtime.h>

typedef unsigned long long u64;
static const unsigned FULL = 0xFFFFFFFFu;

// ---- packed f32x2 helpers ----
__device__ __forceinline__ u64 pk2(float lo, float hi) {
    u64 r;
    asm("mov.b64 %0, {%1, %2};" : "=l"(r) : "f"(lo), "f"(hi));
    return r;
}
__device__ __forceinline__ void upk2(u64 a, float& lo, float& hi) {
    asm("mov.b64 {%0, %1}, %2;" : "=f"(lo), "=f"(hi) : "l"(a));
}
__device__ __forceinline__ u64 fma2(u64 a, u64 b, u64 c) {
    u64 d;
    asm("fma.rn.f32x2 %0, %1, %2, %3;" : "=l"(d) : "l"(a), "l"(b), "l"(c));
    return d;
}
__device__ __forceinline__ u64 mul2(u64 a, u64 b) {
    u64 d;
    asm("mul.rn.f32x2 %0, %1, %2;" : "=l"(d) : "l"(a), "l"(b));
    return d;
}

__host__ __device__ constexpr int PC4(int t) {
    return (t & 1) + ((t >> 1) & 1) + ((t >> 2) & 1) + ((t >> 3) & 1);
}
__host__ __device__ constexpr int PC3(int a) {
    return (a & 1) + ((a >> 1) & 1) + ((a >> 2) & 1);
}

// Compile-time group-index tables (replace the old runtime e_index/o_index
// loops that burned ~250 serial instrs per phase-2 thread).
// Even-parity set {0,3,5,6}, odd {1,2,4,7}; order = (a asc, b asc) matching
// the phase-3 enumeration.
__device__ const signed char E_IDX[8][8] = {
    //        0   1   2   3   4   5   6   7
    /*0*/ { -1, -1, -1,  0, -1,  1,  2, -1 },
    /*1*/ { -1, -1,  3, -1,  4, -1, -1,  5 },
    /*2*/ { -1, -1, -1, -1,  6, -1, -1,  7 },
    /*3*/ { -1, -1, -1, -1, -1,  8,  9, -1 },
    /*4*/ { -1, -1, -1, -1, -1, -1, -1, 10 },
    /*5*/ { -1, -1, -1, -1, -1, -1, 11, -1 },
    /*6*/ { -1, -1, -1, -1, -1, -1, -1, -1 },
    /*7*/ { -1, -1, -1, -1, -1, -1, -1, -1 },
};
__device__ const signed char O_IDX[8][8] = {
    //        0   1   2   3   4   5   6   7
    /*0*/ { -1,  0,  1, -1,  2, -1, -1,  3 },
    /*1*/ { -1, -1, -1,  4, -1,  5,  6, -1 },
    /*2*/ { -1, -1, -1,  7, -1,  8,  9, -1 },
    /*3*/ { -1, -1, -1, -1, 10, -1, -1, 11 },
    /*4*/ { -1, -1, -1, -1, -1, 12, 13, -1 },
    /*5*/ { -1, -1, -1, -1, -1, -1, -1, 14 },
    /*6*/ { -1, -1, -1, -1, -1, -1, -1, 15 },
    /*7*/ { -1, -1, -1, -1, -1, -1, -1, -1 },
};

// One fully-inlined circuit layer on the shuffle-distributed state
// (2 amps/lane: lane bits 4..1 = qubits 0..3, lane bit 0 = qubit 4,
//  register index = qubit 5). ws/wc precomputed.
__device__ __forceinline__ void layer_step(float& r0, float& r1, int lane,
                                           const float* ws, const float* wc) {
    // CNOT ring: (0,1)(1,2)(2,3)(3,4) in lane bits
#pragma unroll
    for (int w = 0; w < 4; w++) {
        const int cm = 16 >> w, tm = 8 >> w;
        float t0 = __shfl_xor_sync(FULL, r0, tm);
        float t1 = __shfl_xor_sync(FULL, r1, tm);
        if (lane & cm) { r0 = t0; r1 = t1; }
    }
    // (4,5): control lane bit0, target in-register
    if (lane & 1) { float t = r0; r0 = r1; r1 = t; }
    // (5,0): control r-index, target lane bit4
    r1 = __shfl_xor_sync(FULL, r1, 16);
    // RY on qubits 0..4 (lane bits), then qubit 5 (in-register)
#pragma unroll
    for (int w = 0; w < 5; w++) {
        const int m = 16 >> w;
        float o0 = __shfl_xor_sync(FULL, r0, m);
        float o1 = __shfl_xor_sync(FULL, r1, m);
        float sg = (lane & m) ? ws[w] : -ws[w];
        r0 = fmaf(sg, o0, wc[w] * r0);
        r1 = fmaf(sg, o1, wc[w] * r1);
    }
    float n0 = fmaf(-ws[5], r1, wc[5] * r0);
    float n1 = fmaf(ws[5], r0, wc[5] * r1);
    r0 = n0; r1 = n1;
}

// ---------------------------------------------------------------------------
// Fused kernel, 512 threads/block, one sample per thread.
// ---------------------------------------------------------------------------
__global__ void __launch_bounds__(512) qfused_kernel(
    const float* __restrict__ x,
    const float* __restrict__ W,
    const float* __restrict__ ab,
    float* __restrict__ out,
    int nlayers, int B)
{
    __shared__ __align__(16) float sM[16][68];   // rows 16B-aligned
    __shared__ __align__(16) float sC[36 * 8];

    const int tid = threadIdx.x;
    const int lane = tid & 31;
    const int wp = tid >> 5;  // warp id = basis column index t (bit3 = qubit0)
    const int gid = blockIdx.x * 512 + tid;

    // ---- all global loads issued up front (max MLP; latencies overlap) ----
    float4 xv = make_float4(0.f, 0.f, 0.f, 0.f);
    if (gid < B) xv = reinterpret_cast<const float4*>(x)[gid];
    float2 abv = *reinterpret_cast<const float2*>(ab);
    float4 wv0, wv1, wv2;
    const bool fast2 = (nlayers == 2);
    if (fast2) {
        const float4* W4 = reinterpret_cast<const float4*>(W);
        wv0 = W4[0]; wv1 = W4[1]; wv2 = W4[2];
    }

    // ---------------- Phase 0: per-sample T-vector build ----------------
    float c0, s0, c1, s1, c2, s2, c3, s3;
    __sincosf(0.5f * xv.x, &s0, &c0);
    __sincosf(0.5f * xv.y, &s1, &c1);
    __sincosf(0.5f * xv.z, &s2, &c2);
    __sincosf(0.5f * xv.w, &s3, &c3);

    float f0[2] = {c0, s0}, f1[2] = {c1, s1}, f2[2] = {c2, s2};
    float t2a[4], t3a[8];
#pragma unroll
    for (int a = 0; a < 2; a++)
#pragma unroll
        for (int b = 0; b < 2; b++) t2a[a * 2 + b] = f0[a] * f1[b];
#pragma unroll
    for (int a = 0; a < 4; a++)
#pragma unroll
        for (int b = 0; b < 2; b++) t3a[a * 2 + b] = t2a[a] * f2[b];

    const u64 cs3 = pk2(c3, s3);
    const u64 sc3 = pk2(s3, c3);
    u64 Tp[8], Ts[8];  // Tp[a] = (T[2a], T[2a+1]),  Ts[a] = swapped
#pragma unroll
    for (int a = 0; a < 8; a++) {
        u64 dd = pk2(t3a[a], t3a[a]);
        Tp[a] = mul2(dd, cs3);
        Ts[a] = mul2(dd, sc3);
    }

    // ---------------- Phase 1: shuffle-based column propagation ------------
    {
        float ca0, sa0, ca1, sa1;
        __sincosf(0.5f * abv.x, &sa0, &ca0);
        __sincosf(0.5f * abv.y, &sa1, &ca1);
        float Ae0 = ca0 * ca1, Ae1 = ca0 * sa1;  // q4=0
        float Ao0 = sa0 * ca1, Ao1 = sa0 * sa1;  // q4=1
        const bool hit = ((lane >> 1) == wp);
        float r0, r1;
        if (lane & 1) { r0 = hit ? Ao0 : 0.f; r1 = hit ? Ao1 : 0.f; }
        else          { r0 = hit ? Ae0 : 0.f; r1 = hit ? Ae1 : 0.f; }

        if (fast2) {
            // all 12 weight sincos computed up front, independent MUFUs;
            // both layers fully unrolled -> chain is pure SHFL + FMA
            float wsa[6], wca[6], wsb[6], wcb[6];
            __sincosf(0.5f * wv0.x, &wsa[0], &wca[0]);
            __sincosf(0.5f * wv0.y, &wsa[1], &wca[1]);
            __sincosf(0.5f * wv0.z, &wsa[2], &wca[2]);
            __sincosf(0.5f * wv0.w, &wsa[3], &wca[3]);
            __sincosf(0.5f * wv1.x, &wsa[4], &wca[4]);
            __sincosf(0.5f * wv1.y, &wsa[5], &wca[5]);
            __sincosf(0.5f * wv1.z, &wsb[0], &wcb[0]);
            __sincosf(0.5f * wv1.w, &wsb[1], &wcb[1]);
            __sincosf(0.5f * wv2.x, &wsb[2], &wcb[2]);
            __sincosf(0.5f * wv2.y, &wsb[3], &wcb[3]);
            __sincosf(0.5f * wv2.z, &wsb[4], &wcb[4]);
            __sincosf(0.5f * wv2.w, &wsb[5], &wcb[5]);
            layer_step(r0, r1, lane, wsa, wca);
            layer_step(r0, r1, lane, wsb, wcb);
        } else {
            for (int l = 0; l < nlayers; l++) {
                float ws[6], wc[6];
#pragma unroll
                for (int w = 0; w < 6; w++)
                    __sincosf(0.5f * __ldg(&W[l * 6 + w]), &ws[w], &wc[w]);
                layer_step(r0, r1, lane, ws, wc);
            }
        }
        sM[wp][2 * lane]     = r0;  // b bit0 = qubit5
        sM[wp][2 * lane + 1] = r1;
    }
    __syncthreads();

    // ---------------- Phase 2: coefficient table (LDS.128-vectorized) ------
    if (tid < 256) {
        const int t = tid >> 4, tb = tid & 15;
        if (t <= tb && (((PC4(t) ^ PC4(tb)) & 1) == 0)) {
            float a0 = 0.f, a1 = 0.f, a2 = 0.f, a3 = 0.f;
#pragma unroll
            for (int i = 0; i < 16; i++) {
                float4 u = *reinterpret_cast<const float4*>(&sM[t][4 * i]);
                float4 v = *reinterpret_cast<const float4*>(&sM[tb][4 * i]);
                float pr = u.x * v.x + u.y * v.y + u.z * v.z + u.w * v.w;
                const int b = 4 * i;
                a0 += (b & 32) ? -pr : pr;  // qubit 0
                a1 += (b & 16) ? -pr : pr;  // qubit 1
                a2 += (b & 8)  ? -pr : pr;  // qubit 2
                a3 += (b & 4)  ? -pr : pr;  // qubit 3
            }
            const int d = (PC4(t) - PC4(tb)) & 3;  // chi = +1 (d==0) / -1 (d==2)
            const float f = (d == 0 ? 1.f : -1.f) * (t == tb ? 1.f : 2.f);
            const int a = t >> 1, i2 = t & 1, b2 = tb >> 1, jj = tb & 1;
            int j, slot;
            if (a == b2)       { j = a;                       slot = i2; }
            else if (i2 == jj) { j = 8 + (int)E_IDX[a][b2];   slot = i2; }
            else               { j = 20 + (int)O_IDX[a][b2];  slot = i2; }
            sC[j * 8 + 0 + slot] = f * a0;
            sC[j * 8 + 2 + slot] = f * a1;
            sC[j * 8 + 4 + slot] = f * a2;
            sC[j * 8 + 6 + slot] = f * a3;
        }
    }
    __syncthreads();

    // ---------------- Phase 3: per-sample quadratic form ----------------
    if (gid >= B) return;

    u64 acc0 = 0ULL, acc1 = 0ULL, acc2 = 0ULL, acc3 = 0ULL;

#define ACCUM(J, PP) do {                                                     \
        u64 pp_ = (PP);                                                       \
        const ulonglong2* q_ = reinterpret_cast<const ulonglong2*>(&sC[(J) * 8]); \
        ulonglong2 qa_ = q_[0], qb_ = q_[1];                                  \
        acc0 = fma2(qa_.x, pp_, acc0);                                        \
        acc1 = fma2(qa_.y, pp_, acc1);                                        \
        acc2 = fma2(qb_.x, pp_, acc2);                                        \
        acc3 = fma2(qb_.y, pp_, acc3);                                        \
    } while (0)

    // diag groups j = 0..7:  (T2a^2, T2a+1^2)
#pragma unroll
    for (int a = 0; a < 8; a++) ACCUM(a, mul2(Tp[a], Tp[a]));
    // E groups j = 8..19: (T2a*T2b, T2a+1*T2b+1), same pc3 parity
    {
        int j = 8;
#pragma unroll
        for (int a = 0; a < 8; a++)
#pragma unroll
            for (int b = a + 1; b < 8; b++)
                if (((PC3(a) ^ PC3(b)) & 1) == 0) { ACCUM(j, mul2(Tp[a], Tp[b])); j++; }
    }
    // O groups j = 20..35: (T2a*T2b+1, T2a+1*T2b), different pc3 parity
    {
        int j = 20;
#pragma unroll
        for (int a = 0; a < 8; a++)
#pragma unroll
            for (int b = a + 1; b < 8; b++)
                if (((PC3(a) ^ PC3(b)) & 1) == 1) { ACCUM(j, mul2(Tp[a], Ts[b])); j++; }
    }
#undef ACCUM

    float lo, hi;
    float4 o;
    upk2(acc0, lo, hi); o.x = lo + hi;
    upk2(acc1, lo, hi); o.y = lo + hi;
    upk2(acc2, lo, hi); o.z = lo + hi;
    upk2(acc3, lo, hi); o.w = lo + hi;
    reinterpret_cast<float4*>(out)[gid] = o;
}

extern "C" void kernel_launch(void* const* d_in, const int* in_sizes, int n_in,
                              void* d_out, int out_size) {
    const float* x  = (const float*)d_in[0];   // (B, 4)
    const float* W  = (const float*)d_in[1];   // (NL, 6)
    const float* ab = (const float*)d_in[2];   // (2,)
    float* out = (float*)d_out;                // (B, 4)
    const int B = in_sizes[0] / 4;
    const int nlayers = in_sizes[1] / 6;
    const int threads = 512;
    const int blocks = (B + threads - 1) / threads;
    qfused_kernel<<<blocks, threads>>>(x, W, ab, out, nlayers, B);
}